// round 15
// baseline (speedup 1.0000x reference)
#include <cuda_runtime.h>
#include <math.h>

#define N_NODES 50000
#define B 64
#define M 32
#define E 128
#define H 8

// scratch (allocation-free rule: __device__ globals)
__device__ float g_zsum[B * E];
__device__ float g_cnt[B];
__device__ float g_wv[B * E];        // tanh(write_values)
__device__ float g_att2[B * M * H];
__device__ float g_mvwo[B * M * E];  // mv @ Wo

// ---------------------------------------------------------------------------
__global__ void kzero() {
    int i = blockIdx.x * 256 + threadIdx.x;
    if (i < B * E) g_zsum[i] = 0.f;
    if (i < B) g_cnt[i] = 0.f;
}

// ---------------------------------------------------------------------------
// kS: zsum[g] = segment_sum(z), cnt[g] = node count. 256 nodes/block.
// ---------------------------------------------------------------------------
__global__ void kS(const float* __restrict__ z, const int* __restrict__ batch) {
    __shared__ int bats[256];
    const int tid = threadIdx.x;
    const int nb0 = blockIdx.x * 256;
    const int nvalid = min(256, N_NODES - nb0);
    bats[tid] = (tid < nvalid) ? batch[nb0 + tid] : -1;
    __syncthreads();

    const int c = tid & 127;
    const int base = (tid >> 7) * 128;
    float run = 0.f, runc = 0.f;
    int curg = -1;
#pragma unroll 4
    for (int j = 0; j < 128; j++) {
        int node = base + j;
        int g = bats[node];
        if (g != curg) {
            if (curg >= 0) {
                atomicAdd(&g_zsum[curg * E + c], run);
                if (c == 0) atomicAdd(&g_cnt[curg], runc);
            }
            curg = g; run = 0.f; runc = 0.f;
        }
        if (g >= 0) {
            run += z[(size_t)(nb0 + node) * E + c];
            runc += 1.f;
        }
    }
    if (curg >= 0) {
        atomicAdd(&g_zsum[curg * E + c], run);
        if (c == 0) atomicAdd(&g_cnt[curg], runc);
    }
}

// ---------------------------------------------------------------------------
// kP: one block per graph b: mvWo, att2, tanh(write_values)
// ---------------------------------------------------------------------------
__global__ void __launch_bounds__(256, 1)
kP(const float* __restrict__ mv, const float* __restrict__ Wo,
   const float* __restrict__ Wa2, const float* __restrict__ ba2,
   const float* __restrict__ Wv, const float* __restrict__ bv) {
    extern __shared__ float sp[];
    float* Wos = sp;            // [128][128]
    float* mvs = sp + E * E;    // [32][128]
    const int b = blockIdx.x, tid = threadIdx.x;

    for (int i = tid; i < E * E / 4; i += 256)
        ((float4*)Wos)[i] = ((const float4*)Wo)[i];
    for (int i = tid; i < M * E / 4; i += 256)
        ((float4*)mvs)[i] = ((const float4*)(mv + (size_t)b * M * E))[i];
    __syncthreads();

    // mvWo: thread tile 4 m-rows x 4 cols
    {
        const int cg = tid & 31;
        const int mb = (tid >> 5) * 4;
        float acc[4][4];
#pragma unroll
        for (int j = 0; j < 4; j++)
            acc[j][0] = acc[j][1] = acc[j][2] = acc[j][3] = 0.f;
        for (int kq = 0; kq < 32; kq++) {
            const float4* wrow = (const float4*)(Wos + kq * 4 * E) + cg;
            float4 w0 = wrow[0], w1 = wrow[32], w2 = wrow[64], w3 = wrow[96];
#pragma unroll
            for (int j = 0; j < 4; j++) {
                float4 zv = ((const float4*)(mvs + (mb + j) * E))[kq];
                acc[j][0] += zv.x * w0.x + zv.y * w1.x + zv.z * w2.x + zv.w * w3.x;
                acc[j][1] += zv.x * w0.y + zv.y * w1.y + zv.z * w2.y + zv.w * w3.y;
                acc[j][2] += zv.x * w0.z + zv.y * w1.z + zv.z * w2.z + zv.w * w3.z;
                acc[j][3] += zv.x * w0.w + zv.y * w1.w + zv.z * w2.w + zv.w * w3.w;
            }
        }
#pragma unroll
        for (int j = 0; j < 4; j++)
            ((float4*)(g_mvwo + (size_t)b * M * E + (mb + j) * E))[cg] =
                make_float4(acc[j][0], acc[j][1], acc[j][2], acc[j][3]);
    }

    // att2: thread = (m, h)
    {
        const int m = tid >> 3, h = tid & 7;
        const float* row = mvs + m * E;
        float s = 0.f;
#pragma unroll 8
        for (int e = 0; e < E; e++) s += row[e] * Wa2[e * H + h];
        g_att2[(b * M + m) * H + h] = s + ba2[h];
    }

    // write_values: threads 0..127, col c
    if (tid < E) {
        float s = g_cnt[b] * bv[tid];
        const float* zs = g_zsum + b * E;
#pragma unroll 8
        for (int k = 0; k < E; k++) s += zs[k] * Wv[k * E + tid];
        g_wv[b * E + tid] = tanhf(s);
    }
}

// ---------------------------------------------------------------------------
// kATT: warp per node (R12 shape), but TRANSPOSED coef layout:
//   lane = q*8 + h  (q = slot-quarter 0..3 owning slots q*8..q*8+7, h = head)
//   -> all 8 head-softmaxes parallel across lanes; reductions span 4/8 lanes.
// ---------------------------------------------------------------------------
__global__ void __launch_bounds__(256)
kATT(const float* __restrict__ z, const int* __restrict__ batch,
     const float* __restrict__ bias_mask,
     const float* __restrict__ Wa1, const float* __restrict__ ba1,
     const float* __restrict__ Wh, const float* __restrict__ bh,
     const float* __restrict__ bo, float* __restrict__ out) {
    __shared__ float wa1t[H * E];   // [h][k]
    const int tid = threadIdx.x;
    for (int i = tid; i < E * H; i += 256) {
        int h = i >> 7, k = i & 127;
        wa1t[h * E + k] = Wa1[k * H + h];
    }
    __syncthreads();

    const int lane = tid & 31;
    const int q = lane >> 3;        // slot quarter
    const int h = lane & 7;         // head
    const int n = blockIdx.x * 8 + (tid >> 5);   // grid = 6250 * 8 = 50000 exact
    const int g = batch[n];

    // --- att1[h] = z[n] @ Wa1[:,h] + ba1[h]; partial over k in q's 32-range ---
    float p = 0.f;
    {
        const float4* zr = (const float4*)(z + (size_t)n * E) + q * 8;
        const float4* wr = (const float4*)(wa1t + h * E) + q * 8;
#pragma unroll
        for (int i = 0; i < 8; i++) {
            float4 a = zr[i], w = wr[i];
            p += a.x * w.x + a.y * w.y + a.z * w.z + a.w * w.w;
        }
    }
    p += __shfl_xor_sync(0xffffffffu, p, 8);
    p += __shfl_xor_sync(0xffffffffu, p, 16);
    const float att1h = p + ba1[h];

    // --- logits for slots q*8+mi, head h ---
    float lh[8];
    float mx = -3.4e38f;
    {
        const float* a2p = g_att2 + ((size_t)g * M + q * 8) * H + h;
        const float* bmp = bias_mask + g * M + q * 8;
#pragma unroll
        for (int mi = 0; mi < 8; mi++) {
            float l = att1h + a2p[mi * H];
            l = (l >= 0.f) ? l : 0.01f * l;         // leaky_relu
            l += (bmp[mi] - 1.f) * 1e9f;
            lh[mi] = l;
            mx = fmaxf(mx, l);
        }
    }
    // softmax over 32 slots within head h (lanes h, h+8, h+16, h+24)
    mx = fmaxf(mx, __shfl_xor_sync(0xffffffffu, mx, 8));
    mx = fmaxf(mx, __shfl_xor_sync(0xffffffffu, mx, 16));
    float s = 0.f;
#pragma unroll
    for (int mi = 0; mi < 8; mi++) { lh[mi] = __expf(lh[mi] - mx); s += lh[mi]; }
    s += __shfl_xor_sync(0xffffffffu, s, 8);
    s += __shfl_xor_sync(0xffffffffu, s, 16);

    // --- head aggregation: w[mi] = bh0 + sum_h coef * Wh[h] ---
    float wv[8];
    const float f = Wh[h] / s;
#pragma unroll
    for (int mi = 0; mi < 8; mi++) wv[mi] = lh[mi] * f;
#pragma unroll
    for (int off = 1; off < 8; off <<= 1)
#pragma unroll
        for (int mi = 0; mi < 8; mi++)
            wv[mi] += __shfl_xor_sync(0xffffffffu, wv[mi], off);
    const float bh0 = bh[0];
#pragma unroll
    for (int mi = 0; mi < 8; mi++) wv[mi] += bh0;

    // --- second softmax over all 32 slots ---
    float mx2 = -3.4e38f;
#pragma unroll
    for (int mi = 0; mi < 8; mi++) mx2 = fmaxf(mx2, wv[mi]);
    mx2 = fmaxf(mx2, __shfl_xor_sync(0xffffffffu, mx2, 8));
    mx2 = fmaxf(mx2, __shfl_xor_sync(0xffffffffu, mx2, 16));
    float s2 = 0.f;
#pragma unroll
    for (int mi = 0; mi < 8; mi++) { wv[mi] = __expf(wv[mi] - mx2); s2 += wv[mi]; }
    s2 += __shfl_xor_sync(0xffffffffu, s2, 8);
    s2 += __shfl_xor_sync(0xffffffffu, s2, 16);
    const float inv2 = 1.f / s2;
#pragma unroll
    for (int mi = 0; mi < 8; mi++) wv[mi] *= inv2;   // final coefs (slots q*8+mi)

    // --- einsum: out[n] = sum_m c_m * mvWo[g][m] + bo (lane owns 4 cols) ---
    float4 acc;
    {
        float4 bo4 = ((const float4*)bo)[lane];
        acc = bo4;
    }
    const float4* mw = (const float4*)(g_mvwo + (size_t)g * M * E);
#pragma unroll
    for (int m = 0; m < M; m++) {
        // coef for slot m lives in lanes q=m>>3 (all h identical); pick h=m&7
        float cm = __shfl_sync(0xffffffffu, wv[m & 7], ((m >> 3) << 3) + (m & 7));
        float4 v = mw[m * 32 + lane];
        acc.x += cm * v.x; acc.y += cm * v.y;
        acc.z += cm * v.z; acc.w += cm * v.w;
    }
    ((float4*)(out + (size_t)n * E))[lane] = acc;
}

// ---------------------------------------------------------------------------
// k2: state updates + arange
// out layout: [output N*E | arange N | new_mv B*M*E | new_write_mask | new_bias_mask]
// ---------------------------------------------------------------------------
__global__ void k2_final(const float* __restrict__ mv,
                         const float* __restrict__ write_mask,
                         const float* __restrict__ bias_mask,
                         float* __restrict__ out) {
    int idx = blockIdx.x * blockDim.x + threadIdx.x;
    const size_t OUT1 = (size_t)N_NODES * E;
    const size_t OUT2 = OUT1 + N_NODES;
    const size_t OUT3 = OUT2 + (size_t)B * M * E;
    const size_t OUT4 = OUT3 + (size_t)B * M;
    if (idx < B * M * E) {
        int b = idx >> 12;
        int m = (idx >> 7) & 31;
        out[OUT2 + idx] = mv[idx] + g_wv[b * E + (idx & 127)] * write_mask[b * M + m];
    }
    if (idx < B * M) {
        int b = idx >> 5, m = idx & 31;
        out[OUT3 + idx] = write_mask[b * M + ((m + 31) & 31)];        // roll(+1)
        out[OUT4 + idx] = fminf(bias_mask[idx] + write_mask[idx], 1.f);
    }
    if (idx < N_NODES) out[OUT1 + idx] = (float)idx;                  // arange
}

// ---------------------------------------------------------------------------
extern "C" void kernel_launch(void* const* d_in, const int* in_sizes, int n_in,
                              void* d_out, int out_size) {
    const float* z     = (const float*)d_in[0];
    const int*   batch = (const int*)d_in[1];
    const float* mv    = (const float*)d_in[2];
    const float* wm    = (const float*)d_in[3];
    const float* bm    = (const float*)d_in[4];
    const float* Wv    = (const float*)d_in[5];
    const float* bv    = (const float*)d_in[6];
    const float* Wo    = (const float*)d_in[7];
    const float* bo    = (const float*)d_in[8];
    const float* Wa1   = (const float*)d_in[9];
    const float* ba1   = (const float*)d_in[10];
    const float* Wa2   = (const float*)d_in[11];
    const float* ba2   = (const float*)d_in[12];
    const float* Wh    = (const float*)d_in[13];
    const float* bh    = (const float*)d_in[14];
    float* out = (float*)d_out;

    const int SMEM_P = (E * E + M * E) * 4;   // 80 KB
    cudaFuncSetAttribute(kP, cudaFuncAttributeMaxDynamicSharedMemorySize, SMEM_P);

    kzero<<<32, 256>>>();
    kS<<<(N_NODES + 255) / 256, 256>>>(z, batch);
    kP<<<B, 256, SMEM_P>>>(mv, Wo, Wa2, ba2, Wv, bv);
    kATT<<<N_NODES / 8, 256>>>(z, batch, bm, Wa1, ba1, Wh, bh, bo, out);
    k2_final<<<(B * M * E + 255) / 256, 256>>>(mv, wm, bm, out);
}

// round 16
// speedup vs baseline: 1.2232x; 1.2232x over previous
#include <cuda_runtime.h>
#include <math.h>

#define N_NODES 50000
#define B 64
#define M 32
#define E 128
#define H 8

// scratch (allocation-free rule: __device__ globals)
__device__ float g_zsum[B * E];
__device__ float g_cnt[B];
__device__ float g_att2[B * M * H];
__device__ float g_mvwo[B * M * E];        // mv @ Wo
__device__ float g_coefs[(size_t)N_NODES * M];

// ---------------------------------------------------------------------------
__global__ void kzero() {
    int i = blockIdx.x * 256 + threadIdx.x;
    if (i < B * E) g_zsum[i] = 0.f;
    if (i < B) g_cnt[i] = 0.f;
}

// ---------------------------------------------------------------------------
// kS: zsum[g] = segment_sum(z), cnt[g] = node count. 256 nodes/block.
// ---------------------------------------------------------------------------
__global__ void kS(const float* __restrict__ z, const int* __restrict__ batch) {
    __shared__ int bats[256];
    const int tid = threadIdx.x;
    const int nb0 = blockIdx.x * 256;
    const int nvalid = min(256, N_NODES - nb0);
    bats[tid] = (tid < nvalid) ? batch[nb0 + tid] : -1;
    __syncthreads();

    const int c = tid & 127;
    const int base = (tid >> 7) * 128;
    float run = 0.f, runc = 0.f;
    int curg = -1;
#pragma unroll 4
    for (int j = 0; j < 128; j++) {
        int node = base + j;
        int g = bats[node];
        if (g != curg) {
            if (curg >= 0) {
                atomicAdd(&g_zsum[curg * E + c], run);
                if (c == 0) atomicAdd(&g_cnt[curg], runc);
            }
            curg = g; run = 0.f; runc = 0.f;
        }
        if (g >= 0) {
            run += z[(size_t)(nb0 + node) * E + c];
            runc += 1.f;
        }
    }
    if (curg >= 0) {
        atomicAdd(&g_zsum[curg * E + c], run);
        if (c == 0) atomicAdd(&g_cnt[curg], runc);
    }
}

// ---------------------------------------------------------------------------
// kP: one block per graph b: mvWo, att2, write_values + ALL state outputs
// ---------------------------------------------------------------------------
__global__ void __launch_bounds__(256, 1)
kP(const float* __restrict__ mv, const float* __restrict__ Wo,
   const float* __restrict__ Wa2, const float* __restrict__ ba2,
   const float* __restrict__ Wv, const float* __restrict__ bv,
   const float* __restrict__ write_mask, const float* __restrict__ bias_mask,
   float* __restrict__ out) {
    extern __shared__ float sp[];
    float* Wos = sp;            // [128][128]
    float* mvs = sp + E * E;    // [32][128]
    float* wvs = mvs + M * E;   // [128]
    const int b = blockIdx.x, tid = threadIdx.x;

    for (int i = tid; i < E * E / 4; i += 256)
        ((float4*)Wos)[i] = ((const float4*)Wo)[i];
    for (int i = tid; i < M * E / 4; i += 256)
        ((float4*)mvs)[i] = ((const float4*)(mv + (size_t)b * M * E))[i];
    __syncthreads();

    // mvWo: thread tile 4 m-rows x 4 cols
    {
        const int cg = tid & 31;
        const int mb = (tid >> 5) * 4;
        float acc[4][4];
#pragma unroll
        for (int j = 0; j < 4; j++)
            acc[j][0] = acc[j][1] = acc[j][2] = acc[j][3] = 0.f;
        for (int kq = 0; kq < 32; kq++) {
            const float4* wrow = (const float4*)(Wos + kq * 4 * E) + cg;
            float4 w0 = wrow[0], w1 = wrow[32], w2 = wrow[64], w3 = wrow[96];
#pragma unroll
            for (int j = 0; j < 4; j++) {
                float4 zv = ((const float4*)(mvs + (mb + j) * E))[kq];
                acc[j][0] += zv.x * w0.x + zv.y * w1.x + zv.z * w2.x + zv.w * w3.x;
                acc[j][1] += zv.x * w0.y + zv.y * w1.y + zv.z * w2.y + zv.w * w3.y;
                acc[j][2] += zv.x * w0.z + zv.y * w1.z + zv.z * w2.z + zv.w * w3.z;
                acc[j][3] += zv.x * w0.w + zv.y * w1.w + zv.z * w2.w + zv.w * w3.w;
            }
        }
#pragma unroll
        for (int j = 0; j < 4; j++)
            ((float4*)(g_mvwo + (size_t)b * M * E + (mb + j) * E))[cg] =
                make_float4(acc[j][0], acc[j][1], acc[j][2], acc[j][3]);
    }

    // att2: thread = (m, h)
    {
        const int m = tid >> 3, h = tid & 7;
        const float* row = mvs + m * E;
        float s = 0.f;
#pragma unroll 8
        for (int e = 0; e < E; e++) s += row[e] * Wa2[e * H + h];
        g_att2[(b * M + m) * H + h] = s + ba2[h];
    }

    // write_values: threads 0..127, col c -> smem
    if (tid < E) {
        float s = g_cnt[b] * bv[tid];
        const float* zs = g_zsum + b * E;
#pragma unroll 8
        for (int k = 0; k < E; k++) s += zs[k] * Wv[k * E + tid];
        wvs[tid] = tanhf(s);
    }
    __syncthreads();

    // state outputs (merged k2)
    const size_t OUT1 = (size_t)N_NODES * E;
    const size_t OUT2 = OUT1 + N_NODES;
    const size_t OUT3 = OUT2 + (size_t)B * M * E;
    const size_t OUT4 = OUT3 + (size_t)B * M;
    for (int i = tid; i < M * E; i += 256) {
        int m = i >> 7, c = i & 127;
        out[OUT2 + (size_t)b * M * E + i] = mvs[i] + wvs[c] * write_mask[b * M + m];
    }
    if (tid < M) {
        out[OUT3 + b * M + tid] = write_mask[b * M + ((tid + 31) & 31)];  // roll(+1)
        out[OUT4 + b * M + tid] =
            fminf(bias_mask[b * M + tid] + write_mask[b * M + tid], 1.f);
    }
}

// ---------------------------------------------------------------------------
// kCOEF: warp per node (R12-proven shape). Writes coefs[n][32].
// ---------------------------------------------------------------------------
__global__ void __launch_bounds__(256)
kCOEF(const float* __restrict__ z, const int* __restrict__ batch,
      const float* __restrict__ bias_mask,
      const float* __restrict__ Wa1, const float* __restrict__ ba1,
      const float* __restrict__ Wh, const float* __restrict__ bh) {
    __shared__ float wa1t[H * E];   // [h][k]
    const int tid = threadIdx.x;
    for (int i = tid; i < E * H; i += 256) {
        int h = i >> 7, k = i & 127;
        wa1t[h * E + k] = Wa1[k * H + h];
    }
    __syncthreads();

    const int lane = tid & 31;
    const int n = blockIdx.x * 8 + (tid >> 5);   // 6250*8 = 50000 exact
    const int g = batch[n];

    float4 z4 = ((const float4*)(z + (size_t)n * E))[lane];
    float a2v[8];
    {
        const float4* a2p = (const float4*)(g_att2 + ((size_t)g * M + lane) * H);
        float4 x = a2p[0], y = a2p[1];
        a2v[0] = x.x; a2v[1] = x.y; a2v[2] = x.z; a2v[3] = x.w;
        a2v[4] = y.x; a2v[5] = y.y; a2v[6] = y.z; a2v[7] = y.w;
    }
    const float biasm = (bias_mask[g * M + lane] - 1.f) * 1e9f;
    const float whv = (lane < H) ? Wh[lane] : 0.f;

    float w = bh[0];
#pragma unroll
    for (int h = 0; h < H; h++) {
        float4 w4 = ((const float4*)(wa1t + h * E))[lane];
        float p = z4.x * w4.x + z4.y * w4.y + z4.z * w4.z + z4.w * w4.w;
#pragma unroll
        for (int off = 16; off > 0; off >>= 1)
            p += __shfl_xor_sync(0xffffffffu, p, off);
        float l = p + ba1[h] + a2v[h];
        l = (l >= 0.f) ? l : 0.01f * l;   // leaky_relu
        l += biasm;
        float mx = l;
#pragma unroll
        for (int off = 16; off > 0; off >>= 1)
            mx = fmaxf(mx, __shfl_xor_sync(0xffffffffu, mx, off));
        float e = __expf(l - mx);
        float s = e;
#pragma unroll
        for (int off = 16; off > 0; off >>= 1)
            s += __shfl_xor_sync(0xffffffffu, s, off);
        w += (e / s) * __shfl_sync(0xffffffffu, whv, h);
    }
    float mx2 = w;
#pragma unroll
    for (int off = 16; off > 0; off >>= 1)
        mx2 = fmaxf(mx2, __shfl_xor_sync(0xffffffffu, mx2, off));
    float e2 = __expf(w - mx2);
    float s2 = e2;
#pragma unroll
    for (int off = 16; off > 0; off >>= 1)
        s2 += __shfl_xor_sync(0xffffffffu, s2, off);

    g_coefs[(size_t)n * M + lane] = e2 / s2;
}

// ---------------------------------------------------------------------------
// kOUT: einsum as a smem GEMM. 256 nodes/block, 256 threads.
//   mvWo for the block's (<=2) graphs staged in smem; coefs staged transposed.
//   Thread tile: 8 nodes x 4 cols, looped x4 over node octets.
// smem: mvs[4096] | mvs2[4096] | cT[32*257] | sb[256 ints]
// ---------------------------------------------------------------------------
#define CPAD 257
__global__ void __launch_bounds__(256)
kOUT(const int* __restrict__ batch, const float* __restrict__ bo,
     float* __restrict__ out) {
    extern __shared__ float sq[];
    float* mvs  = sq;                 // graph g0
    float* mvs2 = sq + M * E;         // graph g1 (if block spans boundary)
    float* cT   = sq + 2 * M * E;     // [32][257]
    int*   sb   = (int*)(cT + M * CPAD);

    const int tid = threadIdx.x;
    const int nb0 = blockIdx.x * 256;
    const int nvalid = min(256, N_NODES - nb0);

    sb[tid] = (tid < nvalid) ? batch[nb0 + tid] : -1;
    __syncthreads();
    const int g0 = sb[0];
    const int g1 = sb[nvalid - 1];

    // stage mvWo for g0 (and g1 if different)
    for (int i = tid; i < M * E / 4; i += 256)
        ((float4*)mvs)[i] = ((const float4*)(g_mvwo + (size_t)g0 * M * E))[i];
    if (g1 != g0)
        for (int i = tid; i < M * E / 4; i += 256)
            ((float4*)mvs2)[i] = ((const float4*)(g_mvwo + (size_t)g1 * M * E))[i];

    // stage coefs transposed: cT[m][j] = coefs[nb0+j][m]  (conflict-free)
#pragma unroll
    for (int k = 0; k < 8; k++) {
        int i4 = k * 256 + tid;          // float4 index
        int j = i4 >> 3, mq = i4 & 7;
        if (j < nvalid) {
            float4 v = ((const float4*)(g_coefs + (size_t)(nb0 + j) * M))[mq];
            cT[(4 * mq + 0) * CPAD + j] = v.x;
            cT[(4 * mq + 1) * CPAD + j] = v.y;
            cT[(4 * mq + 2) * CPAD + j] = v.z;
            cT[(4 * mq + 3) * CPAD + j] = v.w;
        }
    }
    // arange output while we're here
    if (tid < nvalid)
        out[(size_t)N_NODES * E + nb0 + tid] = (float)(nb0 + tid);
    __syncthreads();

    const int cg = tid & 31;          // col group (4 cols)
    const int tj = tid >> 5;          // node octet within 64-node group
    const float4 bo4 = ((const float4*)bo)[cg];

#pragma unroll
    for (int r = 0; r < 4; r++) {
        const int lbase = r * 64 + tj * 8;    // local node base
        const int n0t = nb0 + lbase;
        if (n0t >= N_NODES) continue;
        const int tail = min(8, N_NODES - n0t);

        const float* mwsrc = nullptr;
        if (tail == 8) {
            int gf = sb[lbase], gl = sb[lbase + 7];
            if (gf == gl) mwsrc = (gf == g0) ? mvs : ((gf == g1) ? mvs2 : nullptr);
        }

        if (mwsrc) {
            float4 acc[8];
#pragma unroll
            for (int j = 0; j < 8; j++) acc[j] = bo4;
            for (int m = 0; m < M; m++) {
                float4 v = ((const float4*)mwsrc)[m * 32 + cg];
                const float* crow = cT + m * CPAD + lbase;
#pragma unroll
                for (int j = 0; j < 8; j++) {
                    float cm = crow[j];                 // broadcast LDS
                    acc[j].x += cm * v.x; acc[j].y += cm * v.y;
                    acc[j].z += cm * v.z; acc[j].w += cm * v.w;
                }
            }
#pragma unroll
            for (int j = 0; j < 8; j++)
                ((float4*)(out + (size_t)(n0t + j) * E))[cg] = acc[j];
        } else {
            // boundary tile: per-node global path (rare)
            for (int j = 0; j < tail; j++) {
                int g = sb[lbase + j];
                const float4* mw = (const float4*)(g_mvwo + (size_t)g * M * E);
                float4 acc = bo4;
#pragma unroll 8
                for (int m = 0; m < M; m++) {
                    float cm = cT[m * CPAD + lbase + j];
                    float4 v = mw[m * 32 + cg];
                    acc.x += cm * v.x; acc.y += cm * v.y;
                    acc.z += cm * v.z; acc.w += cm * v.w;
                }
                ((float4*)(out + (size_t)(n0t + j) * E))[cg] = acc;
            }
        }
    }
}

// ---------------------------------------------------------------------------
extern "C" void kernel_launch(void* const* d_in, const int* in_sizes, int n_in,
                              void* d_out, int out_size) {
    const float* z     = (const float*)d_in[0];
    const int*   batch = (const int*)d_in[1];
    const float* mv    = (const float*)d_in[2];
    const float* wm    = (const float*)d_in[3];
    const float* bm    = (const float*)d_in[4];
    const float* Wv    = (const float*)d_in[5];
    const float* bv    = (const float*)d_in[6];
    const float* Wo    = (const float*)d_in[7];
    const float* bo    = (const float*)d_in[8];
    const float* Wa1   = (const float*)d_in[9];
    const float* ba1   = (const float*)d_in[10];
    const float* Wa2   = (const float*)d_in[11];
    const float* ba2   = (const float*)d_in[12];
    const float* Wh    = (const float*)d_in[13];
    const float* bh    = (const float*)d_in[14];
    float* out = (float*)d_out;

    const int SMEM_P = (E * E + M * E + E) * 4;                    // ~81 KB
    const int SMEM_O = (2 * M * E + M * CPAD) * 4 + 256 * 4;       // ~66 KB
    cudaFuncSetAttribute(kP, cudaFuncAttributeMaxDynamicSharedMemorySize, SMEM_P);
    cudaFuncSetAttribute(kOUT, cudaFuncAttributeMaxDynamicSharedMemorySize, SMEM_O);

    kzero<<<32, 256>>>();
    kS<<<(N_NODES + 255) / 256, 256>>>(z, batch);
    kP<<<B, 256, SMEM_P>>>(mv, Wo, Wa2, ba2, Wv, bv, wm, bm, out);
    kCOEF<<<N_NODES / 8, 256>>>(z, batch, bm, Wa1, ba1, Wh, bh);
    kOUT<<<(N_NODES + 255) / 256, 256, SMEM_O>>>(batch, bo, out);
}

// round 17
// speedup vs baseline: 1.3633x; 1.1145x over previous
#include <cuda_runtime.h>
#include <math.h>

#define N_NODES 50000
#define B 64
#define M 32
#define E 128
#define H 8

// scratch (allocation-free rule: __device__ globals)
__device__ float g_zsum[B * E];
__device__ float g_cnt[B];
__device__ float g_att2[B * M * H];
__device__ float g_a2mx[B * H];            // per (g,h): att2 value at argmax slot
__device__ float g_bmx[B * H];             // per (g,h): bias at argmax slot (0 or -1e9)
__device__ float g_mvwo[B * M * E];        // mv @ Wo
__device__ float g_coefs[(size_t)N_NODES * M];

// ---------------------------------------------------------------------------
__global__ void kzero() {
    int i = blockIdx.x * 256 + threadIdx.x;
    if (i < B * E) g_zsum[i] = 0.f;
    if (i < B) g_cnt[i] = 0.f;
}

// ---------------------------------------------------------------------------
// kS: zsum[g] = segment_sum(z), cnt[g] = node count. 256 nodes/block.
// ---------------------------------------------------------------------------
__global__ void kS(const float* __restrict__ z, const int* __restrict__ batch) {
    __shared__ int bats[256];
    const int tid = threadIdx.x;
    const int nb0 = blockIdx.x * 256;
    const int nvalid = min(256, N_NODES - nb0);
    bats[tid] = (tid < nvalid) ? batch[nb0 + tid] : -1;
    __syncthreads();

    const int c = tid & 127;
    const int base = (tid >> 7) * 128;
    float run = 0.f, runc = 0.f;
    int curg = -1;
#pragma unroll 4
    for (int j = 0; j < 128; j++) {
        int node = base + j;
        int g = bats[node];
        if (g != curg) {
            if (curg >= 0) {
                atomicAdd(&g_zsum[curg * E + c], run);
                if (c == 0) atomicAdd(&g_cnt[curg], runc);
            }
            curg = g; run = 0.f; runc = 0.f;
        }
        if (g >= 0) {
            run += z[(size_t)(nb0 + node) * E + c];
            runc += 1.f;
        }
    }
    if (curg >= 0) {
        atomicAdd(&g_zsum[curg * E + c], run);
        if (c == 0) atomicAdd(&g_cnt[curg], runc);
    }
}

// ---------------------------------------------------------------------------
// kP: one block per graph b: mvWo, att2 (+ per-head argmax), write_values,
//     and all state outputs.
// ---------------------------------------------------------------------------
__global__ void __launch_bounds__(256, 1)
kP(const float* __restrict__ mv, const float* __restrict__ Wo,
   const float* __restrict__ Wa2, const float* __restrict__ ba2,
   const float* __restrict__ Wv, const float* __restrict__ bv,
   const float* __restrict__ write_mask, const float* __restrict__ bias_mask,
   float* __restrict__ out) {
    extern __shared__ float sp[];
    float* Wos   = sp;                 // [128][128]
    float* mvs   = sp + E * E;         // [32][128]
    float* wvs   = mvs + M * E;        // [128]
    float* att2s = wvs + E;            // [32][8]
    const int b = blockIdx.x, tid = threadIdx.x;

    for (int i = tid; i < E * E / 4; i += 256)
        ((float4*)Wos)[i] = ((const float4*)Wo)[i];
    for (int i = tid; i < M * E / 4; i += 256)
        ((float4*)mvs)[i] = ((const float4*)(mv + (size_t)b * M * E))[i];
    __syncthreads();

    // mvWo: thread tile 4 m-rows x 4 cols
    {
        const int cg = tid & 31;
        const int mb = (tid >> 5) * 4;
        float acc[4][4];
#pragma unroll
        for (int j = 0; j < 4; j++)
            acc[j][0] = acc[j][1] = acc[j][2] = acc[j][3] = 0.f;
        for (int kq = 0; kq < 32; kq++) {
            const float4* wrow = (const float4*)(Wos + kq * 4 * E) + cg;
            float4 w0 = wrow[0], w1 = wrow[32], w2 = wrow[64], w3 = wrow[96];
#pragma unroll
            for (int j = 0; j < 4; j++) {
                float4 zv = ((const float4*)(mvs + (mb + j) * E))[kq];
                acc[j][0] += zv.x * w0.x + zv.y * w1.x + zv.z * w2.x + zv.w * w3.x;
                acc[j][1] += zv.x * w0.y + zv.y * w1.y + zv.z * w2.y + zv.w * w3.y;
                acc[j][2] += zv.x * w0.z + zv.y * w1.z + zv.z * w2.z + zv.w * w3.z;
                acc[j][3] += zv.x * w0.w + zv.y * w1.w + zv.z * w2.w + zv.w * w3.w;
            }
        }
#pragma unroll
        for (int j = 0; j < 4; j++)
            ((float4*)(g_mvwo + (size_t)b * M * E + (mb + j) * E))[cg] =
                make_float4(acc[j][0], acc[j][1], acc[j][2], acc[j][3]);
    }

    // att2: thread = (m, h); write global + smem for the argmax pass
    {
        const int m = tid >> 3, h = tid & 7;
        const float* row = mvs + m * E;
        float s = 0.f;
#pragma unroll 8
        for (int e = 0; e < E; e++) s += row[e] * Wa2[e * H + h];
        s += ba2[h];
        g_att2[(b * M + m) * H + h] = s;
        att2s[m * H + h] = s;
    }

    // write_values: threads 0..127, col c -> smem
    if (tid < E) {
        float s = g_cnt[b] * bv[tid];
        const float* zs = g_zsum + b * E;
#pragma unroll 8
        for (int k = 0; k < E; k++) s += zs[k] * Wv[k * E + tid];
        wvs[tid] = tanhf(s);
    }
    __syncthreads();

    // per-head argmax of att2 among unmasked slots (node-independent: leaky is
    // monotonic, att1 common per head, bias splits masked far below unmasked)
    if (tid < H) {
        float bestU = -3.4e38f, bestA = -3.4e38f;
        bool anyU = false;
        for (int m = 0; m < M; m++) {
            float v = att2s[m * H + tid];
            bestA = fmaxf(bestA, v);
            if (bias_mask[b * M + m] > 0.5f) { anyU = true; bestU = fmaxf(bestU, v); }
        }
        g_a2mx[b * H + tid] = anyU ? bestU : bestA;
        g_bmx[b * H + tid]  = anyU ? 0.f : -1e9f;
    }

    // state outputs (merged k2)
    const size_t OUT1 = (size_t)N_NODES * E;
    const size_t OUT2 = OUT1 + N_NODES;
    const size_t OUT3 = OUT2 + (size_t)B * M * E;
    const size_t OUT4 = OUT3 + (size_t)B * M;
    for (int i = tid; i < M * E; i += 256) {
        int m = i >> 7, c = i & 127;
        out[OUT2 + (size_t)b * M * E + i] = mvs[i] + wvs[c] * write_mask[b * M + m];
    }
    if (tid < M) {
        out[OUT3 + b * M + tid] = write_mask[b * M + ((tid + 31) & 31)];  // roll(+1)
        out[OUT4 + b * M + tid] =
            fminf(bias_mask[b * M + tid] + write_mask[b * M + tid], 1.f);
    }
}

// ---------------------------------------------------------------------------
// kCOEF: 2 nodes/warp, 16 lanes/node, 2 slots/lane. Precomputed head-max
//        (no max reductions); butterflies span 16 lanes (4 steps).
//        Grid = 3125 blocks x 16 nodes = 50000 exact.
// ---------------------------------------------------------------------------
__global__ void __launch_bounds__(256)
kCOEF(const float* __restrict__ z, const int* __restrict__ batch,
      const float* __restrict__ bias_mask,
      const float* __restrict__ Wa1, const float* __restrict__ ba1,
      const float* __restrict__ Wh, const float* __restrict__ bh) {
    __shared__ float wa1t[H * E];   // [h][k]
    const int tid = threadIdx.x;
    for (int i = tid; i < E * H; i += 256) {
        int h = i >> 7, k = i & 127;
        wa1t[h * E + k] = Wa1[k * H + h];
    }
    __syncthreads();

    const int lane = tid & 31;
    const int ll = lane & 15;                  // lane-in-node
    const int n = blockIdx.x * 16 + (tid >> 5) * 2 + (lane >> 4);
    const int g = batch[n];

    // z partial range: k = ll*8 .. ll*8+7
    const float4* zr = (const float4*)(z + (size_t)n * E);
    const float4 za = zr[ll * 2], zb = zr[ll * 2 + 1];

    // this lane's 2 slots: s0 = 2*ll, s1 = 2*ll+1
    float a2s0[8], a2s1[8];
    {
        const float4* a2p = (const float4*)(g_att2 + ((size_t)g * M + 2 * ll) * H);
        float4 p0 = a2p[0], p1 = a2p[1], p2 = a2p[2], p3 = a2p[3];
        a2s0[0] = p0.x; a2s0[1] = p0.y; a2s0[2] = p0.z; a2s0[3] = p0.w;
        a2s0[4] = p1.x; a2s0[5] = p1.y; a2s0[6] = p1.z; a2s0[7] = p1.w;
        a2s1[0] = p2.x; a2s1[1] = p2.y; a2s1[2] = p2.z; a2s1[3] = p2.w;
        a2s1[4] = p3.x; a2s1[5] = p3.y; a2s1[6] = p3.z; a2s1[7] = p3.w;
    }
    float2 bm2 = ((const float2*)(bias_mask + g * M))[ll];
    const float b0 = (bm2.x - 1.f) * 1e9f;
    const float b1 = (bm2.y - 1.f) * 1e9f;

    // precomputed per-head max ingredients (uniform per node)
    float amx[8], bmx[8];
    {
        const float4* ap = (const float4*)(g_a2mx + g * H);
        const float4* bp = (const float4*)(g_bmx + g * H);
        float4 a0 = ap[0], a1 = ap[1], c0 = bp[0], c1 = bp[1];
        amx[0] = a0.x; amx[1] = a0.y; amx[2] = a0.z; amx[3] = a0.w;
        amx[4] = a1.x; amx[5] = a1.y; amx[6] = a1.z; amx[7] = a1.w;
        bmx[0] = c0.x; bmx[1] = c0.y; bmx[2] = c0.z; bmx[3] = c0.w;
        bmx[4] = c1.x; bmx[5] = c1.y; bmx[6] = c1.z; bmx[7] = c1.w;
    }

    float w0 = bh[0], w1 = w0;
#pragma unroll
    for (int h = 0; h < H; h++) {
        // att1[h]: partial dot + 4-step butterfly over the 16-lane group
        const float4* wr = (const float4*)(wa1t + h * E);
        float4 wa = wr[ll * 2], wb = wr[ll * 2 + 1];
        float p = za.x * wa.x + za.y * wa.y + za.z * wa.z + za.w * wa.w
                + zb.x * wb.x + zb.y * wb.y + zb.z * wb.z + zb.w * wb.w;
        p += __shfl_xor_sync(0xffffffffu, p, 8);
        p += __shfl_xor_sync(0xffffffffu, p, 4);
        p += __shfl_xor_sync(0xffffffffu, p, 2);
        p += __shfl_xor_sync(0xffffffffu, p, 1);
        const float att1h = p + ba1[h];

        // exact max (same op order as slot logits: leaky, then +bias)
        float t = att1h + amx[h];
        float mxh = ((t >= 0.f) ? t : 0.01f * t) + bmx[h];

        float l0 = att1h + a2s0[h];
        l0 = ((l0 >= 0.f) ? l0 : 0.01f * l0) + b0;
        float l1 = att1h + a2s1[h];
        l1 = ((l1 >= 0.f) ? l1 : 0.01f * l1) + b1;
        float e0 = __expf(l0 - mxh);
        float e1 = __expf(l1 - mxh);
        float s = e0 + e1;
        s += __shfl_xor_sync(0xffffffffu, s, 8);
        s += __shfl_xor_sync(0xffffffffu, s, 4);
        s += __shfl_xor_sync(0xffffffffu, s, 2);
        s += __shfl_xor_sync(0xffffffffu, s, 1);
        const float f = Wh[h] / s;
        w0 += e0 * f;
        w1 += e1 * f;
    }

    // final softmax over the node's 32 slots
    float mx2 = fmaxf(w0, w1);
    mx2 = fmaxf(mx2, __shfl_xor_sync(0xffffffffu, mx2, 8));
    mx2 = fmaxf(mx2, __shfl_xor_sync(0xffffffffu, mx2, 4));
    mx2 = fmaxf(mx2, __shfl_xor_sync(0xffffffffu, mx2, 2));
    mx2 = fmaxf(mx2, __shfl_xor_sync(0xffffffffu, mx2, 1));
    float e0 = __expf(w0 - mx2), e1 = __expf(w1 - mx2);
    float s2 = e0 + e1;
    s2 += __shfl_xor_sync(0xffffffffu, s2, 8);
    s2 += __shfl_xor_sync(0xffffffffu, s2, 4);
    s2 += __shfl_xor_sync(0xffffffffu, s2, 2);
    s2 += __shfl_xor_sync(0xffffffffu, s2, 1);
    const float inv2 = 1.f / s2;

    ((float2*)(g_coefs + (size_t)n * M))[ll] = make_float2(e0 * inv2, e1 * inv2);
}

// ---------------------------------------------------------------------------
// kOUT: einsum as a smem GEMM. 256 nodes/block, 256 threads.
// ---------------------------------------------------------------------------
#define CPAD 257
__global__ void __launch_bounds__(256)
kOUT(const int* __restrict__ batch, const float* __restrict__ bo,
     float* __restrict__ out) {
    extern __shared__ float sq[];
    float* mvs  = sq;                 // graph g0
    float* mvs2 = sq + M * E;         // graph g1
    float* cT   = sq + 2 * M * E;     // [32][257]
    int*   sb   = (int*)(cT + M * CPAD);

    const int tid = threadIdx.x;
    const int nb0 = blockIdx.x * 256;
    const int nvalid = min(256, N_NODES - nb0);

    sb[tid] = (tid < nvalid) ? batch[nb0 + tid] : -1;
    __syncthreads();
    const int g0 = sb[0];
    const int g1 = sb[nvalid - 1];

    for (int i = tid; i < M * E / 4; i += 256)
        ((float4*)mvs)[i] = ((const float4*)(g_mvwo + (size_t)g0 * M * E))[i];
    if (g1 != g0)
        for (int i = tid; i < M * E / 4; i += 256)
            ((float4*)mvs2)[i] = ((const float4*)(g_mvwo + (size_t)g1 * M * E))[i];

#pragma unroll
    for (int k = 0; k < 8; k++) {
        int i4 = k * 256 + tid;
        int j = i4 >> 3, mq = i4 & 7;
        if (j < nvalid) {
            float4 v = ((const float4*)(g_coefs + (size_t)(nb0 + j) * M))[mq];
            cT[(4 * mq + 0) * CPAD + j] = v.x;
            cT[(4 * mq + 1) * CPAD + j] = v.y;
            cT[(4 * mq + 2) * CPAD + j] = v.z;
            cT[(4 * mq + 3) * CPAD + j] = v.w;
        }
    }
    if (tid < nvalid)
        out[(size_t)N_NODES * E + nb0 + tid] = (float)(nb0 + tid);
    __syncthreads();

    const int cg = tid & 31;
    const int tj = tid >> 5;
    const float4 bo4 = ((const float4*)bo)[cg];

#pragma unroll
    for (int r = 0; r < 4; r++) {
        const int lbase = r * 64 + tj * 8;
        const int n0t = nb0 + lbase;
        if (n0t >= N_NODES) continue;
        const int tail = min(8, N_NODES - n0t);

        const float* mwsrc = nullptr;
        if (tail == 8) {
            int gf = sb[lbase], gl = sb[lbase + 7];
            if (gf == gl) mwsrc = (gf == g0) ? mvs : ((gf == g1) ? mvs2 : nullptr);
        }

        if (mwsrc) {
            float4 acc[8];
#pragma unroll
            for (int j = 0; j < 8; j++) acc[j] = bo4;
            for (int m = 0; m < M; m++) {
                float4 v = ((const float4*)mwsrc)[m * 32 + cg];
                const float* crow = cT + m * CPAD + lbase;
#pragma unroll
                for (int j = 0; j < 8; j++) {
                    float cm = crow[j];
                    acc[j].x += cm * v.x; acc[j].y += cm * v.y;
                    acc[j].z += cm * v.z; acc[j].w += cm * v.w;
                }
            }
#pragma unroll
            for (int j = 0; j < 8; j++)
                ((float4*)(out + (size_t)(n0t + j) * E))[cg] = acc[j];
        } else {
            for (int j = 0; j < tail; j++) {
                int g = sb[lbase + j];
                const float4* mw = (const float4*)(g_mvwo + (size_t)g * M * E);
                float4 acc = bo4;
#pragma unroll 8
                for (int m = 0; m < M; m++) {
                    float cm = cT[m * CPAD + lbase + j];
                    float4 v = mw[m * 32 + cg];
                    acc.x += cm * v.x; acc.y += cm * v.y;
                    acc.z += cm * v.z; acc.w += cm * v.w;
                }
                ((float4*)(out + (size_t)(n0t + j) * E))[cg] = acc;
            }
        }
    }
}

// ---------------------------------------------------------------------------
extern "C" void kernel_launch(void* const* d_in, const int* in_sizes, int n_in,
                              void* d_out, int out_size) {
    const float* z     = (const float*)d_in[0];
    const int*   batch = (const int*)d_in[1];
    const float* mv    = (const float*)d_in[2];
    const float* wm    = (const float*)d_in[3];
    const float* bm    = (const float*)d_in[4];
    const float* Wv    = (const float*)d_in[5];
    const float* bv    = (const float*)d_in[6];
    const float* Wo    = (const float*)d_in[7];
    const float* bo    = (const float*)d_in[8];
    const float* Wa1   = (const float*)d_in[9];
    const float* ba1   = (const float*)d_in[10];
    const float* Wa2   = (const float*)d_in[11];
    const float* ba2   = (const float*)d_in[12];
    const float* Wh    = (const float*)d_in[13];
    const float* bh    = (const float*)d_in[14];
    float* out = (float*)d_out;

    const int SMEM_P = (E * E + M * E + E + M * H) * 4;            // ~82 KB
    const int SMEM_O = (2 * M * E + M * CPAD) * 4 + 256 * 4;       // ~66 KB
    cudaFuncSetAttribute(kP, cudaFuncAttributeMaxDynamicSharedMemorySize, SMEM_P);
    cudaFuncSetAttribute(kOUT, cudaFuncAttributeMaxDynamicSharedMemorySize, SMEM_O);

    kzero<<<32, 256>>>();
    kS<<<(N_NODES + 255) / 256, 256>>>(z, batch);
    kP<<<B, 256, SMEM_P>>>(mv, Wo, Wa2, ba2, Wv, bv, wm, bm, out);
    kCOEF<<<N_NODES / 16, 256>>>(z, batch, bm, Wa1, ba1, Wh, bh);
    kOUT<<<(N_NODES + 255) / 256, 256, SMEM_O>>>(batch, bo, out);
}